// round 15
// baseline (speedup 1.0000x reference)
#include <cuda_runtime.h>
#include <cuda_fp16.h>
#include <math.h>
#include <stdint.h>

// Problem dims
constexpr int Bb = 128, Ss = 64, Ee = 256, Hh = 256, Dd = 256, Aa = 256, Vv = 10000;
constexpr int CAT = Dd + 2*Hh + Ee;   // 1024
constexpr int RNK = Ee + 2*Hh;        // 768

// ---------------- scratch ---------------------------------------------------
constexpr size_t OFF_EMB   = 0;
constexpr size_t OFF_XPF   = OFF_EMB   + (size_t)Bb*Ss*Ee;
constexpr size_t OFF_XPB   = OFF_XPF   + (size_t)Bb*Ss*3*Hh;
constexpr size_t OFF_ENCO  = OFF_XPB   + (size_t)Bb*Ss*3*Hh;
constexpr size_t OFF_ENCP  = OFF_ENCO  + (size_t)Bb*Ss*2*Hh;
constexpr size_t OFF_HF0   = OFF_ENCP  + (size_t)Bb*Ss*Aa;
constexpr size_t OFF_HF1   = OFF_HF0   + (size_t)Bb*Hh;
constexpr size_t OFF_HB0   = OFF_HF1   + (size_t)Bb*Hh;
constexpr size_t OFF_HB1   = OFF_HB0   + (size_t)Bb*Hh;
constexpr size_t OFF_HID0  = OFF_HB1   + (size_t)Bb*Hh;
constexpr size_t OFF_HID1  = OFF_HID0  + (size_t)Bb*Dd;
constexpr size_t OFF_FCIN  = OFF_HID1  + (size_t)Bb*Dd;
constexpr size_t OFF_RNIN  = OFF_FCIN  + (size_t)Bb*2*Hh;
constexpr size_t OFF_ATTWT = OFF_RNIN  + (size_t)Bb*RNK;
constexpr size_t OFF_SLOT  = OFF_ATTWT + (size_t)Dd*Aa;
// fp16 planes (stored in float scratch; 2 halves per float)
constexpr size_t OFF_CATHI = OFF_SLOT  + (size_t)2*Bb;
constexpr size_t OFF_CATLO = OFF_CATHI + (size_t)Bb*CAT/2;
constexpr size_t OFF_WHI   = OFF_CATLO + (size_t)Bb*CAT/2;
constexpr size_t OFF_WLO   = OFF_WHI   + (size_t)Vv*CAT/2;
constexpr size_t SCR_TOTAL = OFF_WLO   + (size_t)Vv*CAT/2;

__device__ __align__(256) float g_scratch[SCR_TOTAL];

__device__ __forceinline__ float sigf(float x) { return 1.f / (1.f + expf(-x)); }

__device__ __forceinline__ unsigned int fmono(float x) {
    unsigned int b = __float_as_uint(x);
    return (b & 0x80000000u) ? ~b : (b | 0x80000000u);
}

// fp16 2-way split: x ~= hi + lo (22 mantissa bits captured)
__device__ __forceinline__ void h_split2(float x, __half& hi, __half& lo) {
    hi = __float2half_rn(x);
    lo = __float2half_rn(x - __half2float(hi));
}

#define MMA_F16(d, A0, A1, A2, A3, B0, B1)                                       \
    asm volatile("mma.sync.aligned.m16n8k16.row.col.f32.f16.f16.f32 "            \
                 "{%0,%1,%2,%3}, {%4,%5,%6,%7}, {%8,%9}, {%0,%1,%2,%3};"          \
                 : "+f"(d[0]), "+f"(d[1]), "+f"(d[2]), "+f"(d[3])                 \
                 : "r"(A0), "r"(A1), "r"(A2), "r"(A3), "r"(B0), "r"(B1))

#define LDSM_X4(r0, r1, r2, r3, addr)                                            \
    asm volatile("ldmatrix.sync.aligned.m8n8.x4.shared.b16 {%0,%1,%2,%3}, [%4];" \
                 : "=r"(r0), "=r"(r1), "=r"(r2), "=r"(r3) : "r"(addr))

__device__ __forceinline__ uint32_t smem_u32p(const void* p) {
    uint32_t a;
    asm("{ .reg .u64 t; cvta.to.shared.u64 t, %1; cvt.u32.u64 %0, t; }"
        : "=r"(a) : "l"(p));
    return a;
}

// =====================================================================
//  one-time: split out_W into fp16 hi/lo planes
// =====================================================================
__global__ void split_w_kernel(const float* __restrict__ W,
                               __half* __restrict__ Whi,
                               __half* __restrict__ Wlo, int total)
{
    int i = blockIdx.x * 256 + threadIdx.x;
    if (i < total) {
        __half h, l;
        h_split2(W[i], h, l);
        Whi[i] = h; Wlo[i] = l;
    }
}

// =====================================================================
//  gemmH4: logits GEMM via fp16 mma.sync m16n8k16, 2-way split, 3 terms,
//  ldmatrix fragment loads. BM=32, BN=64 -> grid (157, 4) = 628 blocks
//  (4.24/SM, wave-balanced: makespan 1.18x MMA floor vs 1.41x at 314).
//  128 threads = 4 warps, warp tile 16m x 32n.
//  smem per buffer: Ahi[32][20]w | Alo | Bhi[64][20]w | Blo = 15360 B.
// =====================================================================
__global__ __launch_bounds__(128)
void gemmH4(const __half* __restrict__ Ahi, const __half* __restrict__ Alo,
            const __half* __restrict__ Bhi, const __half* __restrict__ Blo,
            const float* __restrict__ bias,
            float* __restrict__ C, int ldc,
            unsigned long long* __restrict__ slots)
{
    constexpr int K = CAT;
    constexpr int N = Vv;
    constexpr int NCH = K / 32;            // 32 chunks
    constexpr uint32_t BUFB = 15360u;      // bytes per buffer
    __shared__ __align__(16) char smx[2 * 15360];

    const int tid  = threadIdx.x;
    const int lane = tid & 31;
    const int warp = tid >> 5;             // 0..3
    const int wm = warp & 1;               // m half (16 rows)
    const int wn = warp >> 1;              // n half (32 cols)
    const int g = lane >> 2;               // 0..7
    const int t = lane & 3;                // 0..3
    const int row0 = blockIdx.y * 32;
    const int col0 = blockIdx.x * 64;

    // ldmatrix per-lane byte offsets (relative to buffer base)
    const uint32_t aoff =
        (uint32_t)((wm*16 + (lane & 7) + ((lane >> 3) & 1) * 8) * 80
                   + (lane >> 4) * 16);
    const uint32_t boff = (uint32_t)((wn*32 + lane) * 80);
    // plane bases within buffer: Ah 0, Al 2560, Bh 5120, Bl 10240
    const uint32_t sb = smem_u32p(smx);

    // cooperative loads: 6 uint4 slots per thread
    const uint4* srcs[6];
    uint32_t dst[6];
    bool val[6];
    int qq[6];
    #pragma unroll
    for (int h = 0; h < 6; h++) {
        int slot = tid + 128 * h;
        if (slot < 256) {                      // A slots
            int p = slot >> 7;                 // plane
            int r = (slot >> 2) & 31;
            int q = slot & 3;
            srcs[h] = reinterpret_cast<const uint4*>(
                (p ? Alo : Ahi) + (size_t)(row0 + r) * K);
            val[h] = true;
            dst[h] = (uint32_t)(p * 2560 + r * 80 + q * 16);
            qq[h] = q;
        } else {                               // B slots
            int s = slot - 256;
            int p = s >> 8;
            int r = (s >> 2) & 63;
            int q = s & 3;
            int gn = col0 + r;
            val[h] = (gn < N);
            srcs[h] = reinterpret_cast<const uint4*>(
                (p ? Blo : Bhi) + (size_t)(val[h] ? gn : 0) * K);
            dst[h] = (uint32_t)(5120 + p * 5120 + r * 80 + q * 16);
            qq[h] = q;
        }
    }
    const uint4 z4 = make_uint4(0u, 0u, 0u, 0u);

    // preload chunk 0
    uint4 rg[6];
    #pragma unroll
    for (int h = 0; h < 6; h++) rg[h] = val[h] ? srcs[h][qq[h]] : z4;
    #pragma unroll
    for (int h = 0; h < 6; h++)
        *reinterpret_cast<uint4*>(smx + dst[h]) = rg[h];
    __syncthreads();

    float acc[4][4];
    #pragma unroll
    for (int nt = 0; nt < 4; nt++)
        #pragma unroll
        for (int q = 0; q < 4; q++) acc[nt][q] = 0.f;

    int buf = 0;
    for (int ci = 0; ci < NCH; ci++) {
        const bool has_next = (ci + 1 < NCH);
        if (has_next) {
            const int i4 = (ci + 1) * 4;
            #pragma unroll
            for (int h = 0; h < 6; h++)
                rg[h] = val[h] ? srcs[h][i4 + qq[h]] : z4;
        }
        const uint32_t bufb = sb + (uint32_t)buf * BUFB;
        const uint32_t bAh = bufb;
        const uint32_t bAl = bufb + 2560u;
        const uint32_t bBh = bufb + 5120u;
        const uint32_t bBl = bufb + 10240u;
        #pragma unroll
        for (int ks = 0; ks < 2; ks++) {
            const uint32_t kb = (uint32_t)ks * 32u;
            uint32_t Ah[4], Al[4];
            LDSM_X4(Ah[0], Ah[1], Ah[2], Ah[3], bAh + aoff + kb);
            LDSM_X4(Al[0], Al[1], Al[2], Al[3], bAl + aoff + kb);
            uint32_t Bh0[4], Bh1[4], Bl0[4], Bl1[4];
            LDSM_X4(Bh0[0], Bh0[1], Bh0[2], Bh0[3], bBh + boff + kb);
            LDSM_X4(Bh1[0], Bh1[1], Bh1[2], Bh1[3], bBh + boff + kb + 16u);
            LDSM_X4(Bl0[0], Bl0[1], Bl0[2], Bl0[3], bBl + boff + kb);
            LDSM_X4(Bl1[0], Bl1[1], Bl1[2], Bl1[3], bBl + boff + kb + 16u);

            #pragma unroll
            for (int nt = 0; nt < 4; nt++)   // hi*hi
                MMA_F16(acc[nt], Ah[0], Ah[1], Ah[2], Ah[3], Bh0[nt], Bh1[nt]);
            #pragma unroll
            for (int nt = 0; nt < 4; nt++)   // hi*lo
                MMA_F16(acc[nt], Ah[0], Ah[1], Ah[2], Ah[3], Bl0[nt], Bl1[nt]);
            #pragma unroll
            for (int nt = 0; nt < 4; nt++)   // lo*hi
                MMA_F16(acc[nt], Al[0], Al[1], Al[2], Al[3], Bh0[nt], Bh1[nt]);
        }
        if (has_next) {
            const int nb = buf ^ 1;
            __syncthreads();
            #pragma unroll
            for (int h = 0; h < 6; h++)
                *reinterpret_cast<uint4*>(smx + nb * BUFB + dst[h]) = rg[h];
            __syncthreads();
            buf = nb;
        }
    }

    // ---- epilogue: bias, store, fused argmax (proven layout) ----
    const int gm0 = row0 + wm*16 + g;
    const int gm1 = gm0 + 8;
    float best0 = -INFINITY, best1 = -INFINITY;
    int bi0 = 0, bi1 = 0;
    #pragma unroll
    for (int nt = 0; nt < 4; nt++) {
        const int cb = col0 + wn*32 + nt*8;
        if (cb < N) {
            const int c0 = cb + 2*t;
            float bv0 = bias[c0], bv1 = bias[c0 + 1];
            float v00 = acc[nt][0] + bv0;
            float v01 = acc[nt][1] + bv1;
            float v10 = acc[nt][2] + bv0;
            float v11 = acc[nt][3] + bv1;
            *reinterpret_cast<float2*>(&C[(size_t)gm0 * ldc + c0]) = make_float2(v00, v01);
            *reinterpret_cast<float2*>(&C[(size_t)gm1 * ldc + c0]) = make_float2(v10, v11);
            if (v00 > best0) { best0 = v00; bi0 = c0; }
            if (v01 > best0) { best0 = v01; bi0 = c0 + 1; }
            if (v10 > best1) { best1 = v10; bi1 = c0; }
            if (v11 > best1) { best1 = v11; bi1 = c0 + 1; }
        }
    }
    unsigned long long k0p =
        ((unsigned long long)fmono(best0) << 32) |
        (unsigned long long)(0xFFFFFFFFu - (unsigned)bi0);
    unsigned long long k1p =
        ((unsigned long long)fmono(best1) << 32) |
        (unsigned long long)(0xFFFFFFFFu - (unsigned)bi1);
    #pragma unroll
    for (int o = 1; o <= 2; o <<= 1) {
        unsigned long long o0 = __shfl_xor_sync(0xffffffffu, k0p, o);
        unsigned long long o1 = __shfl_xor_sync(0xffffffffu, k1p, o);
        if (o0 > k0p) k0p = o0;
        if (o1 > k1p) k1p = o1;
    }
    if (t == 0) {
        atomicMax(&slots[gm0], k0p);
        atomicMax(&slots[gm1], k1p);
    }
}

// =====================================================================
//  gemmL: big one-time GEMMs (unchanged, passing).
// =====================================================================
__global__ __launch_bounds__(256)
void gemmL(const float* __restrict__ A, int lda,
           const float* __restrict__ Bm, int ldb,
           float* __restrict__ C, int ldc,
           const float* __restrict__ bias,
           int M, int N, int K)
{
    __shared__ __align__(16) float sA[2][16][132];
    __shared__ __align__(16) float sB[2][16][68];
    const int tid = threadIdx.x;
    const int tx = tid & 15, ty = tid >> 4;
    const int row0 = blockIdx.y * 128, col0 = blockIdx.x * 64;
    const int lr = tid >> 2;
    const int lc = (tid & 3) * 4;

    const float* Aptr0 = A + (size_t)(row0 + lr) * lda + lc;
    const float* Aptr1 = A + (size_t)(row0 + 64 + lr) * lda + lc;
    const int gnl = col0 + lr;
    const int gnc = (gnl < N) ? gnl : (N - 1);
    const float* Bptr = Bm + (size_t)gnc * ldb + lc;
    const bool bval = (gnl < N);

    float4 pa0 = *reinterpret_cast<const float4*>(Aptr0);
    float4 pa1 = *reinterpret_cast<const float4*>(Aptr1);
    float4 pb  = *reinterpret_cast<const float4*>(Bptr);
    if (!bval) pb = make_float4(0.f, 0.f, 0.f, 0.f);

    sA[0][lc+0][lr]    = pa0.x; sA[0][lc+1][lr]    = pa0.y;
    sA[0][lc+2][lr]    = pa0.z; sA[0][lc+3][lr]    = pa0.w;
    sA[0][lc+0][64+lr] = pa1.x; sA[0][lc+1][64+lr] = pa1.y;
    sA[0][lc+2][64+lr] = pa1.z; sA[0][lc+3][64+lr] = pa1.w;
    sB[0][lc+0][lr] = pb.x; sB[0][lc+1][lr] = pb.y;
    sB[0][lc+2][lr] = pb.z; sB[0][lc+3][lr] = pb.w;
    __syncthreads();

    float acc[8][4];
    #pragma unroll
    for (int i = 0; i < 8; i++)
        #pragma unroll
        for (int j = 0; j < 4; j++) acc[i][j] = 0.f;

    int buf = 0;
    for (int k0 = 16; k0 <= K; k0 += 16) {
        const bool has_next = (k0 < K);
        if (has_next) {
            pa0 = *reinterpret_cast<const float4*>(Aptr0 + k0);
            pa1 = *reinterpret_cast<const float4*>(Aptr1 + k0);
            pb  = *reinterpret_cast<const float4*>(Bptr + k0);
            if (!bval) pb = make_float4(0.f, 0.f, 0.f, 0.f);
        }
        #pragma unroll
        for (int kk = 0; kk < 16; kk++) {
            float4 av0 = *reinterpret_cast<const float4*>(&sA[buf][kk][ty*8]);
            float4 av1 = *reinterpret_cast<const float4*>(&sA[buf][kk][ty*8+4]);
            float4 bv  = *reinterpret_cast<const float4*>(&sB[buf][kk][tx*4]);
            float a[8] = {av0.x, av0.y, av0.z, av0.w, av1.x, av1.y, av1.z, av1.w};
            float b[4] = {bv.x, bv.y, bv.z, bv.w};
            #pragma unroll
            for (int i = 0; i < 8; i++)
                #pragma unroll
                for (int j = 0; j < 4; j++) acc[i][j] += a[i] * b[j];
        }
        if (has_next) {
            const int nb = buf ^ 1;
            sA[nb][lc+0][lr]    = pa0.x; sA[nb][lc+1][lr]    = pa0.y;
            sA[nb][lc+2][lr]    = pa0.z; sA[nb][lc+3][lr]    = pa0.w;
            sA[nb][lc+0][64+lr] = pa1.x; sA[nb][lc+1][64+lr] = pa1.y;
            sA[nb][lc+2][64+lr] = pa1.z; sA[nb][lc+3][64+lr] = pa1.w;
            sB[nb][lc+0][lr] = pb.x; sB[nb][lc+1][lr] = pb.y;
            sB[nb][lc+2][lr] = pb.z; sB[nb][lc+3][lr] = pb.w;
            __syncthreads();
            buf = nb;
        }
    }

    #pragma unroll
    for (int i = 0; i < 8; i++) {
        const int gm = row0 + ty*8 + i;
        #pragma unroll
        for (int j = 0; j < 4; j++) {
            int gn = col0 + tx*4 + j;
            if (gn < N)
                C[(size_t)gm * ldc + gn] = acc[i][j] + (bias ? bias[gn] : 0.f);
        }
    }
}

// ---------------- small generic GEMM (decoder init only) -------------------
__global__ void gemm32t(const float* __restrict__ A, int lda,
                        const float* __restrict__ Bm, int ldb,
                        float* __restrict__ C, int ldc,
                        const float* __restrict__ bias,
                        int M, int N, int K)
{
    __shared__ float sA[32][33];
    __shared__ float sB[32][33];
    const int tid = threadIdx.x;
    const int tx = tid & 15, ty = tid >> 4;
    const int row0 = blockIdx.y * 32, col0 = blockIdx.x * 32;

    float acc[2][2] = {{0,0},{0,0}};
    for (int k0 = 0; k0 < K; k0 += 32) {
        #pragma unroll
        for (int i = tid; i < 1024; i += 256) {
            int m = i >> 5, kk = i & 31;
            sA[kk][m] = A[(size_t)(row0 + m) * lda + k0 + kk];
            sB[kk][m] = Bm[(size_t)(col0 + m) * ldb + k0 + kk];
        }
        __syncthreads();
        #pragma unroll
        for (int kk = 0; kk < 32; kk++) {
            float a0 = sA[kk][ty*2], a1 = sA[kk][ty*2+1];
            float b0 = sB[kk][tx*2], b1 = sB[kk][tx*2+1];
            acc[0][0] += a0*b0; acc[0][1] += a0*b1;
            acc[1][0] += a1*b0; acc[1][1] += a1*b1;
        }
        __syncthreads();
    }
    #pragma unroll
    for (int i = 0; i < 2; i++)
        #pragma unroll
        for (int j = 0; j < 2; j++) {
            int gm = row0 + ty*2 + i, gn = col0 + tx*2 + j;
            C[(size_t)gm * ldc + gn] = tanhf(acc[i][j] + bias[gn]);
        }
}

// =====================================================================
//  Encoder fused step (unchanged)
// =====================================================================
__global__ __launch_bounds__(256)
void enc_step_kernel(const float* __restrict__ hf_in,  const float* __restrict__ hb_in,
                     float* __restrict__ hf_out, float* __restrict__ hb_out,
                     const float* __restrict__ Whh_f, const float* __restrict__ Whh_b,
                     const float* __restrict__ bhh_f, const float* __restrict__ bhh_b,
                     const float* __restrict__ xpf,   const float* __restrict__ xpb,
                     float* __restrict__ enc_out, int t)
{
    const int dir = blockIdx.z;
    const float* hin  = dir ? hb_in  : hf_in;
    const float* Whh  = dir ? Whh_b  : Whh_f;
    const float* bhh  = dir ? bhh_b  : bhh_f;
    const float* xp   = dir ? xpb    : xpf;
    float*       hout = dir ? hb_out : hf_out;
    const int s = dir ? (Ss - 1 - t) : t;

    const int j0 = blockIdx.x * 32, b0 = blockIdx.y * 32;
    const int tid = threadIdx.x;
    const int tx = tid & 15, ty = tid >> 4;

    __shared__ float sH[16][33];
    __shared__ float sW[3][16][34];

    float acc[2][2][3];
    #pragma unroll
    for (int bi = 0; bi < 2; bi++)
        #pragma unroll
        for (int ji = 0; ji < 2; ji++)
            #pragma unroll
            for (int g = 0; g < 3; g++) acc[bi][ji][g] = 0.f;

    for (int k0 = 0; k0 < Hh; k0 += 16) {
        #pragma unroll
        for (int i = tid; i < 512; i += 256) {
            int b = i >> 4, kk = i & 15;
            sH[kk][b] = hin[(size_t)(b0 + b) * Hh + k0 + kk];
        }
        #pragma unroll
        for (int i = tid; i < 1536; i += 256) {
            int r = i >> 4, kk = i & 15;
            int g = r / 32, j = r % 32;
            sW[g][kk][j] = Whh[(size_t)(g * Hh + j0 + j) * Hh + k0 + kk];
        }
        __syncthreads();
        #pragma unroll
        for (int kk = 0; kk < 16; kk++) {
            float hv[2] = { sH[kk][ty*2], sH[kk][ty*2 + 1] };
            #pragma unroll
            for (int g = 0; g < 3; g++) {
                float w0 = sW[g][kk][tx*2], w1 = sW[g][kk][tx*2 + 1];
                acc[0][0][g] += hv[0] * w0;
                acc[0][1][g] += hv[0] * w1;
                acc[1][0][g] += hv[1] * w0;
                acc[1][1][g] += hv[1] * w1;
            }
        }
        __syncthreads();
    }

    #pragma unroll
    for (int bi = 0; bi < 2; bi++) {
        int b = b0 + ty*2 + bi;
        #pragma unroll
        for (int ji = 0; ji < 2; ji++) {
            int j = j0 + tx*2 + ji;
            float rh = acc[bi][ji][0] + bhh[j];
            float zh = acc[bi][ji][1] + bhh[Hh + j];
            float nh = acc[bi][ji][2] + bhh[2*Hh + j];
            const float* x = xp + ((size_t)b * Ss + s) * (3*Hh);
            float r = sigf(x[j] + rh);
            float z = sigf(x[Hh + j] + zh);
            float n = tanhf(x[2*Hh + j] + r * nh);
            float hv = hin[(size_t)b * Hh + j];
            float hn = (1.f - z) * n + z * hv;
            hout[(size_t)b * Hh + j] = hn;
            enc_out[((size_t)b * Ss + s) * (2*Hh) + dir * Hh + j] = hn;
        }
    }
}

// =====================================================================
//  dec_fused2 (unchanged from round 13, passing)
// =====================================================================
__global__ __launch_bounds__(256)
void dec_fused2(const float* __restrict__ rnin,
                const float* __restrict__ hid_in,
                const float* __restrict__ dec_Wih,
                const float* __restrict__ dec_Whh,
                const float* __restrict__ dec_bih,
                const float* __restrict__ dec_bhh,
                float* __restrict__ hid_out,
                __half* __restrict__ catHi, __half* __restrict__ catLo,
                unsigned long long* __restrict__ slots)
{
    const int j0 = blockIdx.x * 16, b0 = blockIdx.y * 16;
    const int tid = threadIdx.x;
    const int tx = tid & 15;
    const int ty = tid >> 4;

    __shared__ float sH[16][17];
    __shared__ float sW[4][16][17];

    float acc[4] = {0.f, 0.f, 0.f, 0.f};

    for (int k0 = 0; k0 < RNK + Dd; k0 += 16) {
        const bool ih = (k0 < RNK);
        if (tid < 64) {
            int b = tid >> 2, kq = (tid & 3) * 4;
            float4 v = ih
                ? *reinterpret_cast<const float4*>(rnin + (size_t)(b0 + b) * RNK + k0 + kq)
                : *reinterpret_cast<const float4*>(hid_in + (size_t)(b0 + b) * Dd + (k0 - RNK) + kq);
            sH[kq+0][b] = v.x; sH[kq+1][b] = v.y;
            sH[kq+2][b] = v.z; sH[kq+3][b] = v.w;
        }
        {
            int gg = tid >> 6, j = (tid >> 2) & 15, kq = (tid & 3) * 4;
            int jj = j0 + j;
            float4 w = make_float4(0.f, 0.f, 0.f, 0.f);
            if (ih) {
                if (gg != 3)
                    w = *reinterpret_cast<const float4*>(
                        dec_Wih + (size_t)(gg * Dd + jj) * RNK + k0 + kq);
            } else {
                if (gg != 2)
                    w = *reinterpret_cast<const float4*>(
                        dec_Whh + (size_t)(((gg == 3) ? 2 : gg) * Dd + jj) * Dd + (k0 - RNK) + kq);
            }
            sW[gg][kq+0][j] = w.x; sW[gg][kq+1][j] = w.y;
            sW[gg][kq+2][j] = w.z; sW[gg][kq+3][j] = w.w;
        }
        __syncthreads();
        #pragma unroll
        for (int kk = 0; kk < 16; kk++) {
            float hv = sH[kk][ty];
            #pragma unroll
            for (int g = 0; g < 4; g++)
                acc[g] += hv * sW[g][kk][tx];
        }
        __syncthreads();
    }

    const int b = b0 + ty;
    const int j = j0 + tx;
    float r = sigf(acc[0] + dec_bih[j] + dec_bhh[j]);
    float z = sigf(acc[1] + dec_bih[Dd + j] + dec_bhh[Dd + j]);
    float n = tanhf(acc[2] + dec_bih[2*Dd + j] + r * (acc[3] + dec_bhh[2*Dd + j]));
    float hv = hid_in[(size_t)b * Dd + j];
    float hn = (1.f - z) * n + z * hv;
    hid_out[(size_t)b * Dd + j] = hn;
    __half h2, l2;
    h_split2(hn, h2, l2);
    catHi[(size_t)b * CAT + j] = h2;
    catLo[(size_t)b * CAT + j] = l2;
    if (j == 0) slots[b] = 0ull;
}

// ---------------- small helper kernels ------------------------------------
__global__ void init0_kernel(float* hf, float* hb, unsigned long long* slots)
{
    int i = blockIdx.x * 256 + threadIdx.x;
    if (i < Bb * Hh) { hf[i] = 0.f; hb[i] = 0.f; }
    if (i < Bb)
        slots[i] = ((unsigned long long)fmono(0.f) << 32) | 0xFFFFFFFFull;
}

__global__ void embed_kernel(const int* __restrict__ inp,
                             const float* __restrict__ tab,
                             float* __restrict__ emb)
{
    int bs = blockIdx.x, j = threadIdx.x;
    int tk = inp[bs * 2 + 0];
    float m = (float)inp[bs * 2 + 1];
    emb[(size_t)bs * Ee + j] = tab[(size_t)tk * Ee + j] * m;
}

__global__ void transpose_attw_kernel(const float* __restrict__ attn_W,
                                      float* __restrict__ attWT)
{
    int k = blockIdx.x, j = threadIdx.x;
    attWT[(size_t)k * Aa + j] = attn_W[(size_t)j * (Dd + 2*Hh) + k];
}

__global__ void concat_fc_kernel(const float* __restrict__ hf,
                                 const float* __restrict__ hb,
                                 float* __restrict__ fcin)
{
    int b = blockIdx.x, j = threadIdx.x;
    fcin[(size_t)b*2*Hh + j]      = hf[(size_t)b*Hh + j];
    fcin[(size_t)b*2*Hh + Hh + j] = hb[(size_t)b*Hh + j];
}

// attention (with fused hproj) + decoder-token embedding; writes rnin + cat planes
__global__ __launch_bounds__(256)
void attn_embed_kernel(const float* __restrict__ encp,
                       const float* __restrict__ hid,
                       const float* __restrict__ attWT,
                       const float* __restrict__ enc_out,
                       const unsigned long long* __restrict__ slots,
                       const float* __restrict__ tab,
                       float* __restrict__ rnin,
                       __half* __restrict__ catHi, __half* __restrict__ catLo)
{
    int b = blockIdx.x, tid = threadIdx.x;
    int lane = tid & 31, w = tid >> 5;
    __shared__ float shid[Dd];
    __shared__ float shp[Aa];
    __shared__ float salpha[Ss];

    shid[tid] = hid[(size_t)b*Dd + tid];
    __syncthreads();

    float hp = 0.f;
    #pragma unroll 8
    for (int k = 0; k < Dd; k++) hp += shid[k] * attWT[(size_t)k * Aa + tid];
    shp[tid] = hp;
    __syncthreads();

    #pragma unroll
    for (int i = 0; i < 8; i++) {
        int s = w + 8 * i;
        const float* row = encp + ((size_t)b*Ss + s)*Aa;
        float acc = 0.f;
        #pragma unroll
        for (int a = lane; a < Aa; a += 32) acc += tanhf(row[a] + shp[a]);
        #pragma unroll
        for (int o = 16; o; o >>= 1) acc += __shfl_xor_sync(0xffffffffu, acc, o);
        if (lane == 0) salpha[s] = acc;
    }
    __syncthreads();
    if (w == 0) {
        float v0 = salpha[lane], v1 = salpha[lane + 32];
        float m = fmaxf(v0, v1);
        #pragma unroll
        for (int o = 16; o; o >>= 1) m = fmaxf(m, __shfl_xor_sync(0xffffffffu, m, o));
        float e0 = expf(v0 - m), e1 = expf(v1 - m);
        float sum = e0 + e1;
        #pragma unroll
        for (int o = 16; o; o >>= 1) sum += __shfl_xor_sync(0xffffffffu, sum, o);
        float inv = 1.f / sum;
        salpha[lane] = e0 * inv; salpha[lane + 32] = e1 * inv;
    }
    __syncthreads();
    float a0 = 0.f, a1 = 0.f;
    for (int s = 0; s < Ss; s++) {
        float al = salpha[s];
        const float* eo = enc_out + ((size_t)b*Ss + s)*(2*Hh);
        a0 += al * eo[tid];
        a1 += al * eo[Hh + tid];
    }
    rnin[(size_t)b*RNK + Ee + tid]      = a0;
    rnin[(size_t)b*RNK + Ee + Hh + tid] = a1;

    __half h2, l2;
    h_split2(a0, h2, l2);
    catHi[(size_t)b*CAT + Dd + tid] = h2;
    catLo[(size_t)b*CAT + Dd + tid] = l2;
    h_split2(a1, h2, l2);
    catHi[(size_t)b*CAT + Dd + Hh + tid] = h2;
    catLo[(size_t)b*CAT + Dd + Hh + tid] = l2;

    int tk = (int)(0xFFFFFFFFu - (unsigned)(slots[b] & 0xFFFFFFFFull));
    float e = tab[(size_t)tk * Ee + tid];
    rnin[(size_t)b*RNK + tid] = e;
    h_split2(e, h2, l2);
    catHi[(size_t)b*CAT + Dd + 2*Hh + tid] = h2;
    catLo[(size_t)b*CAT + Dd + 2*Hh + tid] = l2;
}

__global__ void logsoftmax_kernel(float* __restrict__ out)
{
    int row = blockIdx.x, tid = threadIdx.x;
    int s = row & (Ss - 1);
    float* p = out + (size_t)row * Vv;
    if (s == 0) {
        float L = logf(expf(1.f) + (float)(Vv - 1));
        for (int v = tid; v < Vv; v += 256) p[v] = (v == 0 ? 1.f : 0.f) - L;
        return;
    }
    constexpr int PT = (Vv + 255) / 256;
    float regs[PT];
    float m = -INFINITY;
    #pragma unroll
    for (int i = 0; i < PT; i++) {
        int v = tid + i * 256;
        if (v < Vv) { regs[i] = p[v]; m = fmaxf(m, regs[i]); }
        else regs[i] = -INFINITY;
    }
    __shared__ float sm[256];
    sm[tid] = m; __syncthreads();
    for (int o = 128; o; o >>= 1) { if (tid < o) sm[tid] = fmaxf(sm[tid], sm[tid+o]); __syncthreads(); }
    m = sm[0]; __syncthreads();
    float sum = 0.f;
    #pragma unroll
    for (int i = 0; i < PT; i++) {
        int v = tid + i * 256;
        if (v < Vv) sum += expf(regs[i] - m);
    }
    sm[tid] = sum; __syncthreads();
    for (int o = 128; o; o >>= 1) { if (tid < o) sm[tid] += sm[tid+o]; __syncthreads(); }
    float ls = m + logf(sm[0]);
    #pragma unroll
    for (int i = 0; i < PT; i++) {
        int v = tid + i * 256;
        if (v < Vv) p[v] = regs[i] - ls;
    }
}

// ---------------- launch helpers ------------------------------------------
static inline dim3 gridL(int M, int N) { return dim3((N + 63) / 64, M / 128); }

extern "C" void kernel_launch(void* const* d_in, const int* in_sizes, int n_in,
                              void* d_out, int out_size)
{
    const int*   inp       = (const int*)  d_in[0];
    const float* emb_table = (const float*)d_in[1];
    const float* Wih_f     = (const float*)d_in[2];
    const float* Whh_f     = (const float*)d_in[3];
    const float* bih_f     = (const float*)d_in[4];
    const float* bhh_f     = (const float*)d_in[5];
    const float* Wih_b     = (const float*)d_in[6];
    const float* Whh_b     = (const float*)d_in[7];
    const float* bih_b     = (const float*)d_in[8];
    const float* bhh_b     = (const float*)d_in[9];
    const float* fc_W      = (const float*)d_in[10];
    const float* fc_b      = (const float*)d_in[11];
    const float* attn_W    = (const float*)d_in[12];
    const float* attn_b    = (const float*)d_in[13];
    const float* dec_Wih   = (const float*)d_in[14];
    const float* dec_Whh   = (const float*)d_in[15];
    const float* dec_bih   = (const float*)d_in[16];
    const float* dec_bhh   = (const float*)d_in[17];
    const float* out_W     = (const float*)d_in[18];
    const float* out_b     = (const float*)d_in[19];
    float* out = (float*)d_out;

    float* scr = nullptr;
    cudaGetSymbolAddress((void**)&scr, g_scratch);
    float* emb   = scr + OFF_EMB;
    float* xpf   = scr + OFF_XPF;
    float* xpb   = scr + OFF_XPB;
    float* enco  = scr + OFF_ENCO;
    float* encp  = scr + OFF_ENCP;
    float* hf0   = scr + OFF_HF0;
    float* hf1   = scr + OFF_HF1;
    float* hb0   = scr + OFF_HB0;
    float* hb1   = scr + OFF_HB1;
    float* hid0  = scr + OFF_HID0;
    float* hid1  = scr + OFF_HID1;
    float* fcin  = scr + OFF_FCIN;
    float* rnin  = scr + OFF_RNIN;
    float* attWT = scr + OFF_ATTWT;
    __half* catHi = (__half*)(scr + OFF_CATHI);
    __half* catLo = (__half*)(scr + OFF_CATLO);
    __half* Whi   = (__half*)(scr + OFF_WHI);
    __half* Wlo   = (__half*)(scr + OFF_WLO);
    unsigned long long* slots = (unsigned long long*)(scr + OFF_SLOT);

    // ---- init + embedding + one-time GEMMs + weight split ----
    init0_kernel<<<(Bb*Hh + 255)/256, 256>>>(hf0, hb0, slots);
    embed_kernel<<<Bb*Ss, 256>>>(inp, emb_table, emb);
    transpose_attw_kernel<<<Dd, Aa>>>(attn_W, attWT);
    split_w_kernel<<<(Vv*CAT + 255)/256, 256>>>(out_W, Whi, Wlo, Vv*CAT);
    gemmL<<<gridL(Bb*Ss, 3*Hh), 256>>>(emb, Ee, Wih_f, Ee, xpf, 3*Hh, bih_f, Bb*Ss, 3*Hh, Ee);
    gemmL<<<gridL(Bb*Ss, 3*Hh), 256>>>(emb, Ee, Wih_b, Ee, xpb, 3*Hh, bih_b, Bb*Ss, 3*Hh, Ee);

    // ---- encoder recurrence ----
    for (int t = 0; t < Ss; t++) {
        const float* hfi = (t & 1) ? hf1 : hf0;
        const float* hbi = (t & 1) ? hb1 : hb0;
        float* hfo = (t & 1) ? hf0 : hf1;
        float* hbo = (t & 1) ? hb0 : hb1;
        enc_step_kernel<<<dim3(8, 4, 2), 256>>>(hfi, hbi, hfo, hbo,
                                                Whh_f, Whh_b, bhh_f, bhh_b,
                                                xpf, xpb, enco, t);
    }

    // ---- decoder init ----
    concat_fc_kernel<<<Bb, 256>>>(hf0, hb0, fcin);
    gemm32t<<<dim3(Dd/32, Bb/32), 256>>>(fcin, 2*Hh, fc_W, 2*Hh, hid0, Dd, fc_b, Bb, Dd, 2*Hh);

    // ---- attention projection of enc_out (one-time) ----
    gemmL<<<gridL(Bb*Ss, Aa), 256>>>(enco, 2*Hh, attn_W + Dd, Dd + 2*Hh, encp, Aa, attn_b, Bb*Ss, Aa, 2*Hh);

    // ---- decoder steps (3 launches each) ----
    const dim3 gH((Vv + 63) / 64, Bb / 32);
    for (int t = 0; t < Ss - 1; t++) {
        const float* hin = (t & 1) ? hid1 : hid0;
        float*       hout = (t & 1) ? hid0 : hid1;
        attn_embed_kernel<<<Bb, 256>>>(encp, hin, attWT, enco, slots, emb_table,
                                       rnin, catHi, catLo);
        dec_fused2<<<dim3(16, 8), 256>>>(rnin, hin, dec_Wih, dec_Whh,
                                         dec_bih, dec_bhh, hout,
                                         catHi, catLo, slots);
        gemmH4<<<gH, 128>>>(catHi, catLo, Whi, Wlo, out_b,
                            out + (size_t)(t + 1) * Vv, Ss * Vv, slots);
    }

    // ---- final log-softmax ----
    logsoftmax_kernel<<<Bb*Ss, 256>>>(out);
}

// round 16
// speedup vs baseline: 1.1027x; 1.1027x over previous
#include <cuda_runtime.h>
#include <cuda_fp16.h>
#include <math.h>
#include <stdint.h>

// Problem dims
constexpr int Bb = 128, Ss = 64, Ee = 256, Hh = 256, Dd = 256, Aa = 256, Vv = 10000;
constexpr int CAT = Dd + 2*Hh + Ee;   // 1024
constexpr int RNK = Ee + 2*Hh;        // 768

// ---------------- scratch ---------------------------------------------------
constexpr size_t OFF_EMB   = 0;
constexpr size_t OFF_XPF   = OFF_EMB   + (size_t)Bb*Ss*Ee;
constexpr size_t OFF_XPB   = OFF_XPF   + (size_t)Bb*Ss*3*Hh;
constexpr size_t OFF_ENCO  = OFF_XPB   + (size_t)Bb*Ss*3*Hh;
constexpr size_t OFF_ENCP  = OFF_ENCO  + (size_t)Bb*Ss*2*Hh;
constexpr size_t OFF_HF0   = OFF_ENCP  + (size_t)Bb*Ss*Aa;
constexpr size_t OFF_HF1   = OFF_HF0   + (size_t)Bb*Hh;
constexpr size_t OFF_HB0   = OFF_HF1   + (size_t)Bb*Hh;
constexpr size_t OFF_HB1   = OFF_HB0   + (size_t)Bb*Hh;
constexpr size_t OFF_HID0  = OFF_HB1   + (size_t)Bb*Hh;
constexpr size_t OFF_HID1  = OFF_HID0  + (size_t)Bb*Dd;
constexpr size_t OFF_FCIN  = OFF_HID1  + (size_t)Bb*Dd;
constexpr size_t OFF_RNIN  = OFF_FCIN  + (size_t)Bb*2*Hh;
constexpr size_t OFF_ATTWT = OFF_RNIN  + (size_t)Bb*RNK;
constexpr size_t OFF_SLOT  = OFF_ATTWT + (size_t)Dd*Aa;
// fp16 planes (stored in float scratch; 2 halves per float)
constexpr size_t OFF_CATHI = OFF_SLOT  + (size_t)2*Bb;
constexpr size_t OFF_CATLO = OFF_CATHI + (size_t)Bb*CAT/2;
constexpr size_t OFF_WHI   = OFF_CATLO + (size_t)Bb*CAT/2;
constexpr size_t OFF_WLO   = OFF_WHI   + (size_t)Vv*CAT/2;
constexpr size_t SCR_TOTAL = OFF_WLO   + (size_t)Vv*CAT/2;

__device__ __align__(256) float g_scratch[SCR_TOTAL];

__device__ __forceinline__ float sigf(float x) { return 1.f / (1.f + expf(-x)); }

__device__ __forceinline__ unsigned int fmono(float x) {
    unsigned int b = __float_as_uint(x);
    return (b & 0x80000000u) ? ~b : (b | 0x80000000u);
}

// fp16 2-way split: x ~= hi + lo (22 mantissa bits captured)
__device__ __forceinline__ void h_split2(float x, __half& hi, __half& lo) {
    hi = __float2half_rn(x);
    lo = __float2half_rn(x - __half2float(hi));
}

#define MMA_F16(d, A0, A1, A2, A3, B0, B1)                                       \
    asm volatile("mma.sync.aligned.m16n8k16.row.col.f32.f16.f16.f32 "            \
                 "{%0,%1,%2,%3}, {%4,%5,%6,%7}, {%8,%9}, {%0,%1,%2,%3};"          \
                 : "+f"(d[0]), "+f"(d[1]), "+f"(d[2]), "+f"(d[3])                 \
                 : "r"(A0), "r"(A1), "r"(A2), "r"(A3), "r"(B0), "r"(B1))

#define LDSM_X4(r0, r1, r2, r3, addr)                                            \
    asm volatile("ldmatrix.sync.aligned.m8n8.x4.shared.b16 {%0,%1,%2,%3}, [%4];" \
                 : "=r"(r0), "=r"(r1), "=r"(r2), "=r"(r3) : "r"(addr))

__device__ __forceinline__ uint32_t smem_u32p(const void* p) {
    uint32_t a;
    asm("{ .reg .u64 t; cvta.to.shared.u64 t, %1; cvt.u32.u64 %0, t; }"
        : "=r"(a) : "l"(p));
    return a;
}

// =====================================================================
//  one-time: split out_W into fp16 hi/lo planes
// =====================================================================
__global__ void split_w_kernel(const float* __restrict__ W,
                               __half* __restrict__ Whi,
                               __half* __restrict__ Wlo, int total)
{
    int i = blockIdx.x * 256 + threadIdx.x;
    if (i < total) {
        __half h, l;
        h_split2(W[i], h, l);
        Whi[i] = h; Wlo[i] = l;
    }
}

// =====================================================================
//  gemmH3: logits GEMM via fp16 mma.sync m16n8k16, 2-way split, 3 terms,
//  ldmatrix fragment loads, grid (157, 2), 128 threads = 4 warps,
//  warp tile 32m x 32n. Round-16 edits on the round-14 champion:
//   - single __syncthreads per chunk (redundant first barrier removed)
//   - lo*hi term into separate accumulator bank (reuse distance 4 -> 16)
// =====================================================================
__global__ __launch_bounds__(128)
void gemmH3(const __half* __restrict__ Ahi, const __half* __restrict__ Alo,
            const __half* __restrict__ Bhi, const __half* __restrict__ Blo,
            const float* __restrict__ bias,
            float* __restrict__ C, int ldc,
            unsigned long long* __restrict__ slots)
{
    constexpr int K = CAT;
    constexpr int N = Vv;
    constexpr int NCH = K / 32;          // 32 chunks
    // [buf][tensor A/B][plane hi/lo][row 64][word 20]
    __shared__ __align__(16) uint32_t sm[2][2][2][64][20];

    const int tid  = threadIdx.x;
    const int lane = tid & 31;
    const int warp = tid >> 5;           // 0..3
    const int wm = warp & 1;             // m half (32 rows)
    const int wn = warp >> 1;            // n half (32 cols)
    const int g = lane >> 2;             // 0..7
    const int t = lane & 3;              // 0..3
    const int row0 = blockIdx.y * 64;
    const int col0 = blockIdx.x * 64;

    // ldmatrix per-lane byte offsets (within a [64][20]-word plane)
    uint32_t aoffA[2];
    #pragma unroll
    for (int mi = 0; mi < 2; mi++) {
        int row = wm*32 + mi*16 + (lane & 7) + ((lane >> 3) & 1) * 8;
        aoffA[mi] = (uint32_t)(row * 80 + (lane >> 4) * 16);
    }
    const uint32_t boff = (uint32_t)((wn*32 + lane) * 80);

    const uint32_t sb = smem_u32p(&sm[0][0][0][0][0]);
    // plane strides: plane=5120B, tensor=10240B, buf=20480B

    // cooperative load: 2 slots per thread, 1 uint4 per (tensor,plane,slot)
    int rw[2], lq[2];
    const uint4 *pAh[2], *pAl[2], *pBh[2], *pBl[2];
    bool bvv[2];
    #pragma unroll
    for (int h = 0; h < 2; h++) {
        int slot = tid + 128 * h;
        rw[h] = slot >> 2;
        lq[h] = slot & 3;
        pAh[h] = reinterpret_cast<const uint4*>(Ahi + (size_t)(row0 + rw[h]) * K);
        pAl[h] = reinterpret_cast<const uint4*>(Alo + (size_t)(row0 + rw[h]) * K);
        int gn = col0 + rw[h];
        bvv[h] = (gn < N);
        pBh[h] = reinterpret_cast<const uint4*>(Bhi + (size_t)(bvv[h] ? gn : 0) * K);
        pBl[h] = reinterpret_cast<const uint4*>(Blo + (size_t)(bvv[h] ? gn : 0) * K);
    }
    const uint4 z4 = make_uint4(0u, 0u, 0u, 0u);

    // preload chunk 0
    uint4 rAh[2], rAl[2], rBh[2], rBl[2];
    #pragma unroll
    for (int h = 0; h < 2; h++) {
        rAh[h] = pAh[h][lq[h]];
        rAl[h] = pAl[h][lq[h]];
        rBh[h] = bvv[h] ? pBh[h][lq[h]] : z4;
        rBl[h] = bvv[h] ? pBl[h][lq[h]] : z4;
    }
    #pragma unroll
    for (int h = 0; h < 2; h++) {
        *reinterpret_cast<uint4*>(&sm[0][0][0][rw[h]][lq[h]*4]) = rAh[h];
        *reinterpret_cast<uint4*>(&sm[0][0][1][rw[h]][lq[h]*4]) = rAl[h];
        *reinterpret_cast<uint4*>(&sm[0][1][0][rw[h]][lq[h]*4]) = rBh[h];
        *reinterpret_cast<uint4*>(&sm[0][1][1][rw[h]][lq[h]*4]) = rBl[h];
    }
    __syncthreads();

    float acc[2][4][4];      // hh + hl terms
    float accB[2][4][4];     // lh term (separate bank, merged at epilogue)
    #pragma unroll
    for (int mi = 0; mi < 2; mi++)
        #pragma unroll
        for (int nt = 0; nt < 4; nt++)
            #pragma unroll
            for (int q = 0; q < 4; q++) { acc[mi][nt][q] = 0.f; accB[mi][nt][q] = 0.f; }

    int buf = 0;
    for (int ci = 0; ci < NCH; ci++) {
        const bool has_next = (ci + 1 < NCH);
        if (has_next) {
            #pragma unroll
            for (int h = 0; h < 2; h++) {
                const int i4 = (ci + 1) * 4 + lq[h];
                rAh[h] = pAh[h][i4];
                rAl[h] = pAl[h][i4];
                rBh[h] = bvv[h] ? pBh[h][i4] : z4;
                rBl[h] = bvv[h] ? pBl[h][i4] : z4;
            }
        }
        const uint32_t bufb = sb + (uint32_t)buf * 20480u;
        const uint32_t bAh = bufb;
        const uint32_t bAl = bufb + 5120u;
        const uint32_t bBh = bufb + 10240u;
        const uint32_t bBl = bufb + 15360u;
        #pragma unroll
        for (int ks = 0; ks < 2; ks++) {
            const uint32_t kb = (uint32_t)ks * 32u;
            uint32_t Ah[2][4], Al[2][4];
            #pragma unroll
            for (int mi = 0; mi < 2; mi++) {
                LDSM_X4(Ah[mi][0], Ah[mi][1], Ah[mi][2], Ah[mi][3], bAh + aoffA[mi] + kb);
                LDSM_X4(Al[mi][0], Al[mi][1], Al[mi][2], Al[mi][3], bAl + aoffA[mi] + kb);
            }
            uint32_t Bh0[4], Bh1[4], Bl0[4], Bl1[4];
            LDSM_X4(Bh0[0], Bh0[1], Bh0[2], Bh0[3], bBh + boff + kb);
            LDSM_X4(Bh1[0], Bh1[1], Bh1[2], Bh1[3], bBh + boff + kb + 16u);
            LDSM_X4(Bl0[0], Bl0[1], Bl0[2], Bl0[3], bBl + boff + kb);
            LDSM_X4(Bl1[0], Bl1[1], Bl1[2], Bl1[3], bBl + boff + kb + 16u);

            #pragma unroll
            for (int mi = 0; mi < 2; mi++)        // hi*hi -> acc
                #pragma unroll
                for (int nt = 0; nt < 4; nt++)
                    MMA_F16(acc[mi][nt], Ah[mi][0], Ah[mi][1], Ah[mi][2], Ah[mi][3], Bh0[nt], Bh1[nt]);
            #pragma unroll
            for (int mi = 0; mi < 2; mi++)        // lo*hi -> accB (independent bank)
                #pragma unroll
                for (int nt = 0; nt < 4; nt++)
                    MMA_F16(accB[mi][nt], Al[mi][0], Al[mi][1], Al[mi][2], Al[mi][3], Bh0[nt], Bh1[nt]);
            #pragma unroll
            for (int mi = 0; mi < 2; mi++)        // hi*lo -> acc (reuse distance 16)
                #pragma unroll
                for (int nt = 0; nt < 4; nt++)
                    MMA_F16(acc[mi][nt], Ah[mi][0], Ah[mi][1], Ah[mi][2], Ah[mi][3], Bl0[nt], Bl1[nt]);
        }
        if (has_next) {
            const int nb = buf ^ 1;
            // single barrier: nb was last READ two iterations ago, behind the
            // previous barrier — safe to overwrite without a pre-store sync.
            #pragma unroll
            for (int h = 0; h < 2; h++) {
                *reinterpret_cast<uint4*>(&sm[nb][0][0][rw[h]][lq[h]*4]) = rAh[h];
                *reinterpret_cast<uint4*>(&sm[nb][0][1][rw[h]][lq[h]*4]) = rAl[h];
                *reinterpret_cast<uint4*>(&sm[nb][1][0][rw[h]][lq[h]*4]) = rBh[h];
                *reinterpret_cast<uint4*>(&sm[nb][1][1][rw[h]][lq[h]*4]) = rBl[h];
            }
            __syncthreads();
            buf = nb;
        }
    }

    // ---- epilogue: merge banks, bias, store, fused argmax ----
    #pragma unroll
    for (int mi = 0; mi < 2; mi++) {
        const int base = row0 + wm*32 + mi*16;
        const int gm0 = base + g;
        const int gm1 = gm0 + 8;
        float best0 = -INFINITY, best1 = -INFINITY;
        int bi0 = 0, bi1 = 0;
        #pragma unroll
        for (int nt = 0; nt < 4; nt++) {
            const int cb = col0 + wn*32 + nt*8;
            if (cb < N) {
                const int c0 = cb + 2*t;
                float bv0 = bias[c0], bv1 = bias[c0 + 1];
                float v00 = acc[mi][nt][0] + accB[mi][nt][0] + bv0;
                float v01 = acc[mi][nt][1] + accB[mi][nt][1] + bv1;
                float v10 = acc[mi][nt][2] + accB[mi][nt][2] + bv0;
                float v11 = acc[mi][nt][3] + accB[mi][nt][3] + bv1;
                *reinterpret_cast<float2*>(&C[(size_t)gm0 * ldc + c0]) = make_float2(v00, v01);
                *reinterpret_cast<float2*>(&C[(size_t)gm1 * ldc + c0]) = make_float2(v10, v11);
                if (v00 > best0) { best0 = v00; bi0 = c0; }
                if (v01 > best0) { best0 = v01; bi0 = c0 + 1; }
                if (v10 > best1) { best1 = v10; bi1 = c0; }
                if (v11 > best1) { best1 = v11; bi1 = c0 + 1; }
            }
        }
        unsigned long long k0p =
            ((unsigned long long)fmono(best0) << 32) |
            (unsigned long long)(0xFFFFFFFFu - (unsigned)bi0);
        unsigned long long k1p =
            ((unsigned long long)fmono(best1) << 32) |
            (unsigned long long)(0xFFFFFFFFu - (unsigned)bi1);
        #pragma unroll
        for (int o = 1; o <= 2; o <<= 1) {
            unsigned long long o0 = __shfl_xor_sync(0xffffffffu, k0p, o);
            unsigned long long o1 = __shfl_xor_sync(0xffffffffu, k1p, o);
            if (o0 > k0p) k0p = o0;
            if (o1 > k1p) k1p = o1;
        }
        if (t == 0) {
            atomicMax(&slots[gm0], k0p);
            atomicMax(&slots[gm1], k1p);
        }
    }
}

// =====================================================================
//  gemmL: big one-time GEMMs (unchanged, passing).
// =====================================================================
__global__ __launch_bounds__(256)
void gemmL(const float* __restrict__ A, int lda,
           const float* __restrict__ Bm, int ldb,
           float* __restrict__ C, int ldc,
           const float* __restrict__ bias,
           int M, int N, int K)
{
    __shared__ __align__(16) float sA[2][16][132];
    __shared__ __align__(16) float sB[2][16][68];
    const int tid = threadIdx.x;
    const int tx = tid & 15, ty = tid >> 4;
    const int row0 = blockIdx.y * 128, col0 = blockIdx.x * 64;
    const int lr = tid >> 2;
    const int lc = (tid & 3) * 4;

    const float* Aptr0 = A + (size_t)(row0 + lr) * lda + lc;
    const float* Aptr1 = A + (size_t)(row0 + 64 + lr) * lda + lc;
    const int gnl = col0 + lr;
    const int gnc = (gnl < N) ? gnl : (N - 1);
    const float* Bptr = Bm + (size_t)gnc * ldb + lc;
    const bool bval = (gnl < N);

    float4 pa0 = *reinterpret_cast<const float4*>(Aptr0);
    float4 pa1 = *reinterpret_cast<const float4*>(Aptr1);
    float4 pb  = *reinterpret_cast<const float4*>(Bptr);
    if (!bval) pb = make_float4(0.f, 0.f, 0.f, 0.f);

    sA[0][lc+0][lr]    = pa0.x; sA[0][lc+1][lr]    = pa0.y;
    sA[0][lc+2][lr]    = pa0.z; sA[0][lc+3][lr]    = pa0.w;
    sA[0][lc+0][64+lr] = pa1.x; sA[0][lc+1][64+lr] = pa1.y;
    sA[0][lc+2][64+lr] = pa1.z; sA[0][lc+3][64+lr] = pa1.w;
    sB[0][lc+0][lr] = pb.x; sB[0][lc+1][lr] = pb.y;
    sB[0][lc+2][lr] = pb.z; sB[0][lc+3][lr] = pb.w;
    __syncthreads();

    float acc[8][4];
    #pragma unroll
    for (int i = 0; i < 8; i++)
        #pragma unroll
        for (int j = 0; j < 4; j++) acc[i][j] = 0.f;

    int buf = 0;
    for (int k0 = 16; k0 <= K; k0 += 16) {
        const bool has_next = (k0 < K);
        if (has_next) {
            pa0 = *reinterpret_cast<const float4*>(Aptr0 + k0);
            pa1 = *reinterpret_cast<const float4*>(Aptr1 + k0);
            pb  = *reinterpret_cast<const float4*>(Bptr + k0);
            if (!bval) pb = make_float4(0.f, 0.f, 0.f, 0.f);
        }
        #pragma unroll
        for (int kk = 0; kk < 16; kk++) {
            float4 av0 = *reinterpret_cast<const float4*>(&sA[buf][kk][ty*8]);
            float4 av1 = *reinterpret_cast<const float4*>(&sA[buf][kk][ty*8+4]);
            float4 bv  = *reinterpret_cast<const float4*>(&sB[buf][kk][tx*4]);
            float a[8] = {av0.x, av0.y, av0.z, av0.w, av1.x, av1.y, av1.z, av1.w};
            float b[4] = {bv.x, bv.y, bv.z, bv.w};
            #pragma unroll
            for (int i = 0; i < 8; i++)
                #pragma unroll
                for (int j = 0; j < 4; j++) acc[i][j] += a[i] * b[j];
        }
        if (has_next) {
            const int nb = buf ^ 1;
            sA[nb][lc+0][lr]    = pa0.x; sA[nb][lc+1][lr]    = pa0.y;
            sA[nb][lc+2][lr]    = pa0.z; sA[nb][lc+3][lr]    = pa0.w;
            sA[nb][lc+0][64+lr] = pa1.x; sA[nb][lc+1][64+lr] = pa1.y;
            sA[nb][lc+2][64+lr] = pa1.z; sA[nb][lc+3][64+lr] = pa1.w;
            sB[nb][lc+0][lr] = pb.x; sB[nb][lc+1][lr] = pb.y;
            sB[nb][lc+2][lr] = pb.z; sB[nb][lc+3][lr] = pb.w;
            __syncthreads();
            buf = nb;
        }
    }

    #pragma unroll
    for (int i = 0; i < 8; i++) {
        const int gm = row0 + ty*8 + i;
        #pragma unroll
        for (int j = 0; j < 4; j++) {
            int gn = col0 + tx*4 + j;
            if (gn < N)
                C[(size_t)gm * ldc + gn] = acc[i][j] + (bias ? bias[gn] : 0.f);
        }
    }
}

// ---------------- small generic GEMM (decoder init only) -------------------
__global__ void gemm32t(const float* __restrict__ A, int lda,
                        const float* __restrict__ Bm, int ldb,
                        float* __restrict__ C, int ldc,
                        const float* __restrict__ bias,
                        int M, int N, int K)
{
    __shared__ float sA[32][33];
    __shared__ float sB[32][33];
    const int tid = threadIdx.x;
    const int tx = tid & 15, ty = tid >> 4;
    const int row0 = blockIdx.y * 32, col0 = blockIdx.x * 32;

    float acc[2][2] = {{0,0},{0,0}};
    for (int k0 = 0; k0 < K; k0 += 32) {
        #pragma unroll
        for (int i = tid; i < 1024; i += 256) {
            int m = i >> 5, kk = i & 31;
            sA[kk][m] = A[(size_t)(row0 + m) * lda + k0 + kk];
            sB[kk][m] = Bm[(size_t)(col0 + m) * ldb + k0 + kk];
        }
        __syncthreads();
        #pragma unroll
        for (int kk = 0; kk < 32; kk++) {
            float a0 = sA[kk][ty*2], a1 = sA[kk][ty*2+1];
            float b0 = sB[kk][tx*2], b1 = sB[kk][tx*2+1];
            acc[0][0] += a0*b0; acc[0][1] += a0*b1;
            acc[1][0] += a1*b0; acc[1][1] += a1*b1;
        }
        __syncthreads();
    }
    #pragma unroll
    for (int i = 0; i < 2; i++)
        #pragma unroll
        for (int j = 0; j < 2; j++) {
            int gm = row0 + ty*2 + i, gn = col0 + tx*2 + j;
            C[(size_t)gm * ldc + gn] = tanhf(acc[i][j] + bias[gn]);
        }
}

// =====================================================================
//  Encoder fused step (unchanged)
// =====================================================================
__global__ __launch_bounds__(256)
void enc_step_kernel(const float* __restrict__ hf_in,  const float* __restrict__ hb_in,
                     float* __restrict__ hf_out, float* __restrict__ hb_out,
                     const float* __restrict__ Whh_f, const float* __restrict__ Whh_b,
                     const float* __restrict__ bhh_f, const float* __restrict__ bhh_b,
                     const float* __restrict__ xpf,   const float* __restrict__ xpb,
                     float* __restrict__ enc_out, int t)
{
    const int dir = blockIdx.z;
    const float* hin  = dir ? hb_in  : hf_in;
    const float* Whh  = dir ? Whh_b  : Whh_f;
    const float* bhh  = dir ? bhh_b  : bhh_f;
    const float* xp   = dir ? xpb    : xpf;
    float*       hout = dir ? hb_out : hf_out;
    const int s = dir ? (Ss - 1 - t) : t;

    const int j0 = blockIdx.x * 32, b0 = blockIdx.y * 32;
    const int tid = threadIdx.x;
    const int tx = tid & 15, ty = tid >> 4;

    __shared__ float sH[16][33];
    __shared__ float sW[3][16][34];

    float acc[2][2][3];
    #pragma unroll
    for (int bi = 0; bi < 2; bi++)
        #pragma unroll
        for (int ji = 0; ji < 2; ji++)
            #pragma unroll
            for (int g = 0; g < 3; g++) acc[bi][ji][g] = 0.f;

    for (int k0 = 0; k0 < Hh; k0 += 16) {
        #pragma unroll
        for (int i = tid; i < 512; i += 256) {
            int b = i >> 4, kk = i & 15;
            sH[kk][b] = hin[(size_t)(b0 + b) * Hh + k0 + kk];
        }
        #pragma unroll
        for (int i = tid; i < 1536; i += 256) {
            int r = i >> 4, kk = i & 15;
            int g = r / 32, j = r % 32;
            sW[g][kk][j] = Whh[(size_t)(g * Hh + j0 + j) * Hh + k0 + kk];
        }
        __syncthreads();
        #pragma unroll
        for (int kk = 0; kk < 16; kk++) {
            float hv[2] = { sH[kk][ty*2], sH[kk][ty*2 + 1] };
            #pragma unroll
            for (int g = 0; g < 3; g++) {
                float w0 = sW[g][kk][tx*2], w1 = sW[g][kk][tx*2 + 1];
                acc[0][0][g] += hv[0] * w0;
                acc[0][1][g] += hv[0] * w1;
                acc[1][0][g] += hv[1] * w0;
                acc[1][1][g] += hv[1] * w1;
            }
        }
        __syncthreads();
    }

    #pragma unroll
    for (int bi = 0; bi < 2; bi++) {
        int b = b0 + ty*2 + bi;
        #pragma unroll
        for (int ji = 0; ji < 2; ji++) {
            int j = j0 + tx*2 + ji;
            float rh = acc[bi][ji][0] + bhh[j];
            float zh = acc[bi][ji][1] + bhh[Hh + j];
            float nh = acc[bi][ji][2] + bhh[2*Hh + j];
            const float* x = xp + ((size_t)b * Ss + s) * (3*Hh);
            float r = sigf(x[j] + rh);
            float z = sigf(x[Hh + j] + zh);
            float n = tanhf(x[2*Hh + j] + r * nh);
            float hv = hin[(size_t)b * Hh + j];
            float hn = (1.f - z) * n + z * hv;
            hout[(size_t)b * Hh + j] = hn;
            enc_out[((size_t)b * Ss + s) * (2*Hh) + dir * Hh + j] = hn;
        }
    }
}

// =====================================================================
//  dec_fused2 (unchanged from round 13, passing)
// =====================================================================
__global__ __launch_bounds__(256)
void dec_fused2(const float* __restrict__ rnin,
                const float* __restrict__ hid_in,
                const float* __restrict__ dec_Wih,
                const float* __restrict__ dec_Whh,
                const float* __restrict__ dec_bih,
                const float* __restrict__ dec_bhh,
                float* __restrict__ hid_out,
                __half* __restrict__ catHi, __half* __restrict__ catLo,
                unsigned long long* __restrict__ slots)
{
    const int j0 = blockIdx.x * 16, b0 = blockIdx.y * 16;
    const int tid = threadIdx.x;
    const int tx = tid & 15;
    const int ty = tid >> 4;

    __shared__ float sH[16][17];
    __shared__ float sW[4][16][17];

    float acc[4] = {0.f, 0.f, 0.f, 0.f};

    for (int k0 = 0; k0 < RNK + Dd; k0 += 16) {
        const bool ih = (k0 < RNK);
        if (tid < 64) {
            int b = tid >> 2, kq = (tid & 3) * 4;
            float4 v = ih
                ? *reinterpret_cast<const float4*>(rnin + (size_t)(b0 + b) * RNK + k0 + kq)
                : *reinterpret_cast<const float4*>(hid_in + (size_t)(b0 + b) * Dd + (k0 - RNK) + kq);
            sH[kq+0][b] = v.x; sH[kq+1][b] = v.y;
            sH[kq+2][b] = v.z; sH[kq+3][b] = v.w;
        }
        {
            int gg = tid >> 6, j = (tid >> 2) & 15, kq = (tid & 3) * 4;
            int jj = j0 + j;
            float4 w = make_float4(0.f, 0.f, 0.f, 0.f);
            if (ih) {
                if (gg != 3)
                    w = *reinterpret_cast<const float4*>(
                        dec_Wih + (size_t)(gg * Dd + jj) * RNK + k0 + kq);
            } else {
                if (gg != 2)
                    w = *reinterpret_cast<const float4*>(
                        dec_Whh + (size_t)(((gg == 3) ? 2 : gg) * Dd + jj) * Dd + (k0 - RNK) + kq);
            }
            sW[gg][kq+0][j] = w.x; sW[gg][kq+1][j] = w.y;
            sW[gg][kq+2][j] = w.z; sW[gg][kq+3][j] = w.w;
        }
        __syncthreads();
        #pragma unroll
        for (int kk = 0; kk < 16; kk++) {
            float hv = sH[kk][ty];
            #pragma unroll
            for (int g = 0; g < 4; g++)
                acc[g] += hv * sW[g][kk][tx];
        }
        __syncthreads();
    }

    const int b = b0 + ty;
    const int j = j0 + tx;
    float r = sigf(acc[0] + dec_bih[j] + dec_bhh[j]);
    float z = sigf(acc[1] + dec_bih[Dd + j] + dec_bhh[Dd + j]);
    float n = tanhf(acc[2] + dec_bih[2*Dd + j] + r * (acc[3] + dec_bhh[2*Dd + j]));
    float hv = hid_in[(size_t)b * Dd + j];
    float hn = (1.f - z) * n + z * hv;
    hid_out[(size_t)b * Dd + j] = hn;
    __half h2, l2;
    h_split2(hn, h2, l2);
    catHi[(size_t)b * CAT + j] = h2;
    catLo[(size_t)b * CAT + j] = l2;
    if (j == 0) slots[b] = 0ull;
}

// ---------------- small helper kernels ------------------------------------
__global__ void init0_kernel(float* hf, float* hb, unsigned long long* slots)
{
    int i = blockIdx.x * 256 + threadIdx.x;
    if (i < Bb * Hh) { hf[i] = 0.f; hb[i] = 0.f; }
    if (i < Bb)
        slots[i] = ((unsigned long long)fmono(0.f) << 32) | 0xFFFFFFFFull;
}

__global__ void embed_kernel(const int* __restrict__ inp,
                             const float* __restrict__ tab,
                             float* __restrict__ emb)
{
    int bs = blockIdx.x, j = threadIdx.x;
    int tk = inp[bs * 2 + 0];
    float m = (float)inp[bs * 2 + 1];
    emb[(size_t)bs * Ee + j] = tab[(size_t)tk * Ee + j] * m;
}

__global__ void transpose_attw_kernel(const float* __restrict__ attn_W,
                                      float* __restrict__ attWT)
{
    int k = blockIdx.x, j = threadIdx.x;
    attWT[(size_t)k * Aa + j] = attn_W[(size_t)j * (Dd + 2*Hh) + k];
}

__global__ void concat_fc_kernel(const float* __restrict__ hf,
                                 const float* __restrict__ hb,
                                 float* __restrict__ fcin)
{
    int b = blockIdx.x, j = threadIdx.x;
    fcin[(size_t)b*2*Hh + j]      = hf[(size_t)b*Hh + j];
    fcin[(size_t)b*2*Hh + Hh + j] = hb[(size_t)b*Hh + j];
}

// attention (with fused hproj) + decoder-token embedding; writes rnin + cat planes
__global__ __launch_bounds__(256)
void attn_embed_kernel(const float* __restrict__ encp,
                       const float* __restrict__ hid,
                       const float* __restrict__ attWT,
                       const float* __restrict__ enc_out,
                       const unsigned long long* __restrict__ slots,
                       const float* __restrict__ tab,
                       float* __restrict__ rnin,
                       __half* __restrict__ catHi, __half* __restrict__ catLo)
{
    int b = blockIdx.x, tid = threadIdx.x;
    int lane = tid & 31, w = tid >> 5;
    __shared__ float shid[Dd];
    __shared__ float shp[Aa];
    __shared__ float salpha[Ss];

    shid[tid] = hid[(size_t)b*Dd + tid];
    __syncthreads();

    float hp = 0.f;
    #pragma unroll 8
    for (int k = 0; k < Dd; k++) hp += shid[k] * attWT[(size_t)k * Aa + tid];
    shp[tid] = hp;
    __syncthreads();

    #pragma unroll
    for (int i = 0; i < 8; i++) {
        int s = w + 8 * i;
        const float* row = encp + ((size_t)b*Ss + s)*Aa;
        float acc = 0.f;
        #pragma unroll
        for (int a = lane; a < Aa; a += 32) acc += tanhf(row[a] + shp[a]);
        #pragma unroll
        for (int o = 16; o; o >>= 1) acc += __shfl_xor_sync(0xffffffffu, acc, o);
        if (lane == 0) salpha[s] = acc;
    }
    __syncthreads();
    if (w == 0) {
        float v0 = salpha[lane], v1 = salpha[lane + 32];
        float m = fmaxf(v0, v1);
        #pragma unroll
        for (int o = 16; o; o >>= 1) m = fmaxf(m, __shfl_xor_sync(0xffffffffu, m, o));
        float e0 = expf(v0 - m), e1 = expf(v1 - m);
        float sum = e0 + e1;
        #pragma unroll
        for (int o = 16; o; o >>= 1) sum += __shfl_xor_sync(0xffffffffu, sum, o);
        float inv = 1.f / sum;
        salpha[lane] = e0 * inv; salpha[lane + 32] = e1 * inv;
    }
    __syncthreads();
    float a0 = 0.f, a1 = 0.f;
    for (int s = 0; s < Ss; s++) {
        float al = salpha[s];
        const float* eo = enc_out + ((size_t)b*Ss + s)*(2*Hh);
        a0 += al * eo[tid];
        a1 += al * eo[Hh + tid];
    }
    rnin[(size_t)b*RNK + Ee + tid]      = a0;
    rnin[(size_t)b*RNK + Ee + Hh + tid] = a1;

    __half h2, l2;
    h_split2(a0, h2, l2);
    catHi[(size_t)b*CAT + Dd + tid] = h2;
    catLo[(size_t)b*CAT + Dd + tid] = l2;
    h_split2(a1, h2, l2);
    catHi[(size_t)b*CAT + Dd + Hh + tid] = h2;
    catLo[(size_t)b*CAT + Dd + Hh + tid] = l2;

    int tk = (int)(0xFFFFFFFFu - (unsigned)(slots[b] & 0xFFFFFFFFull));
    float e = tab[(size_t)tk * Ee + tid];
    rnin[(size_t)b*RNK + tid] = e;
    h_split2(e, h2, l2);
    catHi[(size_t)b*CAT + Dd + 2*Hh + tid] = h2;
    catLo[(size_t)b*CAT + Dd + 2*Hh + tid] = l2;
}

__global__ void logsoftmax_kernel(float* __restrict__ out)
{
    int row = blockIdx.x, tid = threadIdx.x;
    int s = row & (Ss - 1);
    float* p = out + (size_t)row * Vv;
    if (s == 0) {
        float L = logf(expf(1.f) + (float)(Vv - 1));
        for (int v = tid; v < Vv; v += 256) p[v] = (v == 0 ? 1.f : 0.f) - L;
        return;
    }
    constexpr int PT = (Vv + 255) / 256;
    float regs[PT];
    float m = -INFINITY;
    #pragma unroll
    for (int i = 0; i < PT; i++) {
        int v = tid + i * 256;
        if (v < Vv) { regs[i] = p[v]; m = fmaxf(m, regs[i]); }
        else regs[i] = -INFINITY;
    }
    __shared__ float sm[256];
    sm[tid] = m; __syncthreads();
    for (int o = 128; o; o >>= 1) { if (tid < o) sm[tid] = fmaxf(sm[tid], sm[tid+o]); __syncthreads(); }
    m = sm[0]; __syncthreads();
    float sum = 0.f;
    #pragma unroll
    for (int i = 0; i < PT; i++) {
        int v = tid + i * 256;
        if (v < Vv) sum += expf(regs[i] - m);
    }
    sm[tid] = sum; __syncthreads();
    for (int o = 128; o; o >>= 1) { if (tid < o) sm[tid] += sm[tid+o]; __syncthreads(); }
    float ls = m + logf(sm[0]);
    #pragma unroll
    for (int i = 0; i < PT; i++) {
        int v = tid + i * 256;
        if (v < Vv) p[v] = regs[i] - ls;
    }
}

// ---------------- launch helpers ------------------------------------------
static inline dim3 gridL(int M, int N) { return dim3((N + 63) / 64, M / 128); }

extern "C" void kernel_launch(void* const* d_in, const int* in_sizes, int n_in,
                              void* d_out, int out_size)
{
    const int*   inp       = (const int*)  d_in[0];
    const float* emb_table = (const float*)d_in[1];
    const float* Wih_f     = (const float*)d_in[2];
    const float* Whh_f     = (const float*)d_in[3];
    const float* bih_f     = (const float*)d_in[4];
    const float* bhh_f     = (const float*)d_in[5];
    const float* Wih_b     = (const float*)d_in[6];
    const float* Whh_b     = (const float*)d_in[7];
    const float* bih_b     = (const float*)d_in[8];
    const float* bhh_b     = (const float*)d_in[9];
    const float* fc_W      = (const float*)d_in[10];
    const float* fc_b      = (const float*)d_in[11];
    const float* attn_W    = (const float*)d_in[12];
    const float* attn_b    = (const float*)d_in[13];
    const float* dec_Wih   = (const float*)d_in[14];
    const float* dec_Whh   = (const float*)d_in[15];
    const float* dec_bih   = (const float*)d_in[16];
    const float* dec_bhh   = (const float*)d_in[17];
    const float* out_W     = (const float*)d_in[18];
    const float* out_b     = (const float*)d_in[19];
    float* out = (float*)d_out;

    float* scr = nullptr;
    cudaGetSymbolAddress((void**)&scr, g_scratch);
    float* emb   = scr + OFF_EMB;
    float* xpf   = scr + OFF_XPF;
    float* xpb   = scr + OFF_XPB;
    float* enco  = scr + OFF_ENCO;
    float* encp  = scr + OFF_ENCP;
    float* hf0   = scr + OFF_HF0;
    float* hf1   = scr + OFF_HF1;
    float* hb0   = scr + OFF_HB0;
    float* hb1   = scr + OFF_HB1;
    float* hid0  = scr + OFF_HID0;
    float* hid1  = scr + OFF_HID1;
    float* fcin  = scr + OFF_FCIN;
    float* rnin  = scr + OFF_RNIN;
    float* attWT = scr + OFF_ATTWT;
    __half* catHi = (__half*)(scr + OFF_CATHI);
    __half* catLo = (__half*)(scr + OFF_CATLO);
    __half* Whi   = (__half*)(scr + OFF_WHI);
    __half* Wlo   = (__half*)(scr + OFF_WLO);
    unsigned long long* slots = (unsigned long long*)(scr + OFF_SLOT);

    // ---- init + embedding + one-time GEMMs + weight split ----
    init0_kernel<<<(Bb*Hh + 255)/256, 256>>>(hf0, hb0, slots);
    embed_kernel<<<Bb*Ss, 256>>>(inp, emb_table, emb);
    transpose_attw_kernel<<<Dd, Aa>>>(attn_W, attWT);
    split_w_kernel<<<(Vv*CAT + 255)/256, 256>>>(out_W, Whi, Wlo, Vv*CAT);
    gemmL<<<gridL(Bb*Ss, 3*Hh), 256>>>(emb, Ee, Wih_f, Ee, xpf, 3*Hh, bih_f, Bb*Ss, 3*Hh, Ee);
    gemmL<<<gridL(Bb*Ss, 3*Hh), 256>>>(emb, Ee, Wih_b, Ee, xpb, 3*Hh, bih_b, Bb*Ss, 3*Hh, Ee);

    // ---- encoder recurrence ----
    for (int t = 0; t < Ss; t++) {
        const float* hfi = (t & 1) ? hf1 : hf0;
        const float* hbi = (t & 1) ? hb1 : hb0;
        float* hfo = (t & 1) ? hf0 : hf1;
        float* hbo = (t & 1) ? hb0 : hb1;
        enc_step_kernel<<<dim3(8, 4, 2), 256>>>(hfi, hbi, hfo, hbo,
                                                Whh_f, Whh_b, bhh_f, bhh_b,
                                                xpf, xpb, enco, t);
    }

    // ---- decoder init ----
    concat_fc_kernel<<<Bb, 256>>>(hf0, hb0, fcin);
    gemm32t<<<dim3(Dd/32, Bb/32), 256>>>(fcin, 2*Hh, fc_W, 2*Hh, hid0, Dd, fc_b, Bb, Dd, 2*Hh);

    // ---- attention projection of enc_out (one-time) ----
    gemmL<<<gridL(Bb*Ss, Aa), 256>>>(enco, 2*Hh, attn_W + Dd, Dd + 2*Hh, encp, Aa, attn_b, Bb*Ss, Aa, 2*Hh);

    // ---- decoder steps (3 launches each) ----
    const dim3 gH((Vv + 63) / 64, Bb / 64);
    for (int t = 0; t < Ss - 1; t++) {
        const float* hin = (t & 1) ? hid1 : hid0;
        float*       hout = (t & 1) ? hid0 : hid1;
        attn_embed_kernel<<<Bb, 256>>>(encp, hin, attWT, enco, slots, emb_table,
                                       rnin, catHi, catLo);
        dec_fused2<<<dim3(16, 8), 256>>>(rnin, hin, dec_Wih, dec_Whh,
                                         dec_bih, dec_bhh, hout,
                                         catHi, catLo, slots);
        gemmH3<<<gH, 128>>>(catHi, catLo, Whi, Wlo, out_b,
                            out + (size_t)(t + 1) * Vv, Ss * Vv, slots);
    }

    // ---- final log-softmax ----
    logsoftmax_kernel<<<Bb*Ss, 256>>>(out);
}